// round 8
// baseline (speedup 1.0000x reference)
#include <cuda_runtime.h>

// EdgeUpdateNetwork: T=8, N=256, F=128
//
// Factorization: y[t,i,j,f] = A[t,i,f] + B[t,j,f] where
//   A = x @ w[:, :F]^T,  B = x @ w[:, F:]^T
// BN stats in closed form from A/B reductions; then fused
// affine+relu+diag-zero+L1-normalize streaming kernel writes 537MB.

#define T_DIM 8
#define N_DIM 256
#define F_DIM 128
#define M_DIM (T_DIM * N_DIM)   // 2048 rows
#define O_DIM 512               // A1 | B1 | A2 | B2

// Scratch (device globals — no allocation allowed)
__device__ float g_Y[M_DIM * O_DIM];   // 4 MB: Y[m][o]
__device__ float g_sh[4 * F_DIM];      // [br*256 + f] = scale, [br*256+128+f] = shift

// ---------------------------------------------------------------------------
// Kernel 1: X[2048,128] @ W^T[128,512] -> Y[2048,512]
// 64x64 tile, 256 threads (8 warps), 4x4 micro-tile, grid (8,32)=256 blocks
// -> 2048 warps (~14/SM) to cover LDS+FFMA latency. Double-buffered smem:
// ONE __syncthreads per K-chunk (store targets the buffer nobody reads).
// ---------------------------------------------------------------------------
__global__ void __launch_bounds__(256) gemm_kernel(const float* __restrict__ X,
                                                   const float* __restrict__ w1,
                                                   const float* __restrict__ w2) {
    __shared__ float Xs[2][16][68];   // [buf][kk][m]
    __shared__ float Ws[2][16][68];   // [buf][kk][o]

    const int m0 = blockIdx.y * 64;
    const int o0 = blockIdx.x * 64;
    const int tid = threadIdx.x;
    const int tx = tid & 15;          // o: cols tx*4 .. tx*4+3
    const int ty = tid >> 4;          // m: rows ty*4 .. ty*4+3 (ty 0..15)
    const float* wbase = (o0 < 256) ? w1 : w2;   // o0 mult of 64, never straddles

    // Per-chunk loads: X tile 64x16 = 256 float4, 1 per thread; W likewise.
    const int xr = tid >> 2, xq = tid & 3;                 // row 0..63, quad 0..3
    const float* xp = X + (m0 + xr) * 128 + xq * 4;
    const float* wp = wbase + ((o0 + xr) & 127) * 256 + (((o0 + xr) >> 7) & 1) * 128 + xq * 4;

    float acc[4][4] = {};
    float4 px, pw;

    // prefetch chunk 0 and stage into buffer 0
    px = *(const float4*)&xp[0];
    pw = *(const float4*)&wp[0];
    Xs[0][xq * 4 + 0][xr] = px.x;  Xs[0][xq * 4 + 1][xr] = px.y;
    Xs[0][xq * 4 + 2][xr] = px.z;  Xs[0][xq * 4 + 3][xr] = px.w;
    Ws[0][xq * 4 + 0][xr] = pw.x;  Ws[0][xq * 4 + 1][xr] = pw.y;
    Ws[0][xq * 4 + 2][xr] = pw.z;  Ws[0][xq * 4 + 3][xr] = pw.w;
    __syncthreads();

    #pragma unroll
    for (int c = 0; c < 8; c++) {
        const int cur = c & 1, nxt = cur ^ 1;
        if (c < 7) {
            const int kc = (c + 1) * 16;
            px = *(const float4*)&xp[kc];
            pw = *(const float4*)&wp[kc];
        }

        #pragma unroll
        for (int kk = 0; kk < 16; kk++) {
            const float4 xa = *(const float4*)&Xs[cur][kk][ty * 4];
            const float4 wr = *(const float4*)&Ws[cur][kk][tx * 4];
            const float xv[4] = {xa.x, xa.y, xa.z, xa.w};
            const float wv[4] = {wr.x, wr.y, wr.z, wr.w};
            #pragma unroll
            for (int a = 0; a < 4; a++)
                #pragma unroll
                for (int b = 0; b < 4; b++)
                    acc[a][b] = fmaf(xv[a], wv[b], acc[a][b]);
        }

        if (c < 7) {
            // Writing the OTHER buffer: safe while peers read `cur`.
            Xs[nxt][xq * 4 + 0][xr] = px.x;  Xs[nxt][xq * 4 + 1][xr] = px.y;
            Xs[nxt][xq * 4 + 2][xr] = px.z;  Xs[nxt][xq * 4 + 3][xr] = px.w;
            Ws[nxt][xq * 4 + 0][xr] = pw.x;  Ws[nxt][xq * 4 + 1][xr] = pw.y;
            Ws[nxt][xq * 4 + 2][xr] = pw.z;  Ws[nxt][xq * 4 + 3][xr] = pw.w;
            __syncthreads();
        }
    }

    #pragma unroll
    for (int a = 0; a < 4; a++) {
        float4 v = make_float4(acc[a][0], acc[a][1], acc[a][2], acc[a][3]);
        *(float4*)&g_Y[(m0 + ty * 4 + a) * O_DIM + o0 + tx * 4] = v;
    }
}

// ---------------------------------------------------------------------------
// Kernel 2: closed-form BN stats per (branch, f).
//   mean = (sumA + sumB) / (T*N)
//   E[y^2] = (N*(sumA2 + sumB2) + 2*sum_t SA_t*SB_t) / (T*N*N)
//   fold: s = g * rsqrt(var+eps), h = b - mean*s
// ---------------------------------------------------------------------------
__global__ void stats_kernel(const float* __restrict__ gamma1,
                             const float* __restrict__ beta1,
                             const float* __restrict__ gamma2,
                             const float* __restrict__ beta2) {
    const int bf = blockIdx.x;
    const int br = bf >> 7, f = bf & 127;
    const int colA = br * 256 + f;
    const int colB = colA + 128;
    const int tid = threadIdx.x;

    float sa = 0.f, sa2 = 0.f, sb = 0.f, sb2 = 0.f;
    #pragma unroll
    for (int k = 0; k < 8; k++) {
        int m = tid * 8 + k;
        float a = g_Y[m * O_DIM + colA];
        float b = g_Y[m * O_DIM + colB];
        sa += a;  sa2 = fmaf(a, a, sa2);
        sb += b;  sb2 = fmaf(b, b, sb2);
    }
    #pragma unroll
    for (int off = 16; off; off >>= 1) {
        sa  += __shfl_xor_sync(0xffffffffu, sa,  off);
        sa2 += __shfl_xor_sync(0xffffffffu, sa2, off);
        sb  += __shfl_xor_sync(0xffffffffu, sb,  off);
        sb2 += __shfl_xor_sync(0xffffffffu, sb2, off);
    }
    __shared__ float SA[8], SB[8], SA2[8], SB2[8];
    int w = tid >> 5;
    if ((tid & 31) == 0) { SA[w] = sa; SB[w] = sb; SA2[w] = sa2; SB2[w] = sb2; }
    __syncthreads();
    if (tid == 0) {
        float sumA = 0.f, sumB = 0.f, sumA2 = 0.f, sumB2 = 0.f, cross = 0.f;
        #pragma unroll
        for (int t = 0; t < 8; t++) {
            sumA  += SA[t];  sumB  += SB[t];
            sumA2 += SA2[t]; sumB2 += SB2[t];
            cross = fmaf(SA[t], SB[t], cross);
        }
        float mean = (sumA + sumB) * (1.0f / 2048.0f);
        float ey2  = (256.0f * (sumA2 + sumB2) + 2.0f * cross) * (1.0f / 524288.0f);
        float var  = ey2 - mean * mean;
        float g  = br ? gamma2[f] : gamma1[f];
        float bb = br ? beta2[f]  : beta1[f];
        float s  = g * rsqrtf(var + 1e-5f);
        g_sh[br * 256 + f]       = s;
        g_sh[br * 256 + 128 + f] = bb - mean * s;
    }
}

// ---------------------------------------------------------------------------
// Kernel 3: streaming epilogue (write-bound, 537 MB).
// Block = (t, branch, 8-row i-tile); warp w handles j in [w*32, w*32+32).
// j OUTER, i inner: each b4 load is reused for 8 i-rows,
// p[ii] = fma(a,s,h) precomputed in registers. Streaming stores (__stcs).
// ---------------------------------------------------------------------------
__global__ void __launch_bounds__(256) edge_kernel(float* __restrict__ out) {
    const int bid = blockIdx.x;          // 512 blocks
    const int itile = bid & 31;
    const int br = (bid >> 5) & 1;
    const int t = bid >> 6;
    const int i0 = itile * 8;
    const int tid = threadIdx.x;
    const int w = tid >> 5, l = tid & 31;
    const int f0 = l * 4;

    const float4 s4 = *(const float4*)&g_sh[br * 256 + f0];
    const float4 h4 = *(const float4*)&g_sh[br * 256 + 128 + f0];
    const int baseA = br * 256 + f0;
    const int baseB = baseA + 128;

    float4 p[8];
    #pragma unroll
    for (int ii = 0; ii < 8; ii++) {
        const float4 a4 = *(const float4*)&g_Y[(t * 256 + i0 + ii) * O_DIM + baseA];
        p[ii].x = fmaf(a4.x, s4.x, h4.x);
        p[ii].y = fmaf(a4.y, s4.y, h4.y);
        p[ii].z = fmaf(a4.z, s4.z, h4.z);
        p[ii].w = fmaf(a4.w, s4.w, h4.w);
    }

    // out index: (((t*2+br)*256 + i) * 256 + j) * 128 + f
    const size_t outbase = (size_t)((t * 2 + br) * 256 + i0) * (256 * 128);

    #pragma unroll 2
    for (int jj = 0; jj < 32; jj++) {
        const int j = w * 32 + jj;
        const float4 b4 = *(const float4*)&g_Y[(t * 256 + j) * O_DIM + baseB];
        float* orow = out + outbase + (size_t)j * 128 + f0;
        #pragma unroll
        for (int ii = 0; ii < 8; ii++) {
            float vx = fmaxf(fmaf(b4.x, s4.x, p[ii].x), 0.0f);
            float vy = fmaxf(fmaf(b4.y, s4.y, p[ii].y), 0.0f);
            float vz = fmaxf(fmaf(b4.z, s4.z, p[ii].z), 0.0f);
            float vw = fmaxf(fmaf(b4.w, s4.w, p[ii].w), 0.0f);
            if (j == i0 + ii) { vx = 0.f; vy = 0.f; vz = 0.f; vw = 0.f; }
            float sm = (vx + vy) + (vz + vw);
            #pragma unroll
            for (int off = 16; off; off >>= 1)
                sm += __shfl_xor_sync(0xffffffffu, sm, off);
            const float inv = __fdividef(1.0f, fmaxf(sm, 1e-12f));
            float4 o4 = make_float4(vx * inv, vy * inv, vz * inv, vw * inv);
            __stcs((float4*)(orow + (size_t)ii * (256 * 128)), o4);
        }
    }
}

// ---------------------------------------------------------------------------
extern "C" void kernel_launch(void* const* d_in, const int* in_sizes, int n_in,
                              void* d_out, int out_size) {
    const float* x  = (const float*)d_in[0];   // node_feats [8,256,128]
    const float* w1 = (const float*)d_in[1];   // [128,256]
    const float* g1 = (const float*)d_in[2];
    const float* b1 = (const float*)d_in[3];
    const float* w2 = (const float*)d_in[4];
    const float* g2 = (const float*)d_in[5];
    const float* b2 = (const float*)d_in[6];
    float* out = (float*)d_out;                // [8,2,256,256,128] fp32

    dim3 ggrid(O_DIM / 64, M_DIM / 64);        // (8, 32) = 256 blocks
    gemm_kernel<<<ggrid, 256>>>(x, w1, w2);
    stats_kernel<<<256, 256>>>(g1, b1, g2, b2);
    edge_kernel<<<512, 256>>>(out);
}

// round 9
// speedup vs baseline: 1.1626x; 1.1626x over previous
#include <cuda_runtime.h>

// EdgeUpdateNetwork: T=8, N=256, F=128
//
// Factorization: y[t,i,j,f] = A[t,i,f] + B[t,j,f] where
//   A = x @ w[:, :F]^T,  B = x @ w[:, F:]^T
// BN stats in closed form from A/B reductions; then fused
// affine+relu+diag-zero+L1-normalize streaming kernel writes 537MB.

#define T_DIM 8
#define N_DIM 256
#define F_DIM 128
#define M_DIM (T_DIM * N_DIM)   // 2048 rows
#define O_DIM 512               // A1 | B1 | A2 | B2

// Scratch (device globals — no allocation allowed)
__device__ float g_Y[M_DIM * O_DIM];   // 4 MB: Y[m][o]
__device__ float g_sh[4 * F_DIM];      // [br*256 + f] = scale, [br*256+128+f] = shift

// ---------------------------------------------------------------------------
// Kernel 1: X[2048,128] @ W^T[128,512] -> Y[2048,512]
// 64x64 tile, 256 threads (8 warps), 4x4 micro-tile, grid (8,32)=256 blocks.
// Double-buffered smem: ONE __syncthreads per K-chunk.
// ---------------------------------------------------------------------------
__global__ void __launch_bounds__(256) gemm_kernel(const float* __restrict__ X,
                                                   const float* __restrict__ w1,
                                                   const float* __restrict__ w2) {
    __shared__ float Xs[2][16][68];   // [buf][kk][m]
    __shared__ float Ws[2][16][68];   // [buf][kk][o]

    const int m0 = blockIdx.y * 64;
    const int o0 = blockIdx.x * 64;
    const int tid = threadIdx.x;
    const int tx = tid & 15;          // o: cols tx*4 .. tx*4+3
    const int ty = tid >> 4;          // m: rows ty*4 .. ty*4+3 (ty 0..15)
    const float* wbase = (o0 < 256) ? w1 : w2;   // o0 mult of 64, never straddles

    // Per-chunk loads: X tile 64x16 = 256 float4, 1 per thread; W likewise.
    const int xr = tid >> 2, xq = tid & 3;                 // row 0..63, quad 0..3
    const float* xp = X + (m0 + xr) * 128 + xq * 4;
    const float* wp = wbase + ((o0 + xr) & 127) * 256 + (((o0 + xr) >> 7) & 1) * 128 + xq * 4;

    float acc[4][4] = {};
    float4 px, pw;

    // prefetch chunk 0 and stage into buffer 0
    px = *(const float4*)&xp[0];
    pw = *(const float4*)&wp[0];
    Xs[0][xq * 4 + 0][xr] = px.x;  Xs[0][xq * 4 + 1][xr] = px.y;
    Xs[0][xq * 4 + 2][xr] = px.z;  Xs[0][xq * 4 + 3][xr] = px.w;
    Ws[0][xq * 4 + 0][xr] = pw.x;  Ws[0][xq * 4 + 1][xr] = pw.y;
    Ws[0][xq * 4 + 2][xr] = pw.z;  Ws[0][xq * 4 + 3][xr] = pw.w;
    __syncthreads();

    #pragma unroll
    for (int c = 0; c < 8; c++) {
        const int cur = c & 1, nxt = cur ^ 1;
        if (c < 7) {
            const int kc = (c + 1) * 16;
            px = *(const float4*)&xp[kc];
            pw = *(const float4*)&wp[kc];
        }

        #pragma unroll
        for (int kk = 0; kk < 16; kk++) {
            const float4 xa = *(const float4*)&Xs[cur][kk][ty * 4];
            const float4 wr = *(const float4*)&Ws[cur][kk][tx * 4];
            const float xv[4] = {xa.x, xa.y, xa.z, xa.w};
            const float wv[4] = {wr.x, wr.y, wr.z, wr.w};
            #pragma unroll
            for (int a = 0; a < 4; a++)
                #pragma unroll
                for (int b = 0; b < 4; b++)
                    acc[a][b] = fmaf(xv[a], wv[b], acc[a][b]);
        }

        if (c < 7) {
            // Writing the OTHER buffer: safe while peers read `cur`.
            Xs[nxt][xq * 4 + 0][xr] = px.x;  Xs[nxt][xq * 4 + 1][xr] = px.y;
            Xs[nxt][xq * 4 + 2][xr] = px.z;  Xs[nxt][xq * 4 + 3][xr] = px.w;
            Ws[nxt][xq * 4 + 0][xr] = pw.x;  Ws[nxt][xq * 4 + 1][xr] = pw.y;
            Ws[nxt][xq * 4 + 2][xr] = pw.z;  Ws[nxt][xq * 4 + 3][xr] = pw.w;
            __syncthreads();
        }
    }

    #pragma unroll
    for (int a = 0; a < 4; a++) {
        float4 v = make_float4(acc[a][0], acc[a][1], acc[a][2], acc[a][3]);
        *(float4*)&g_Y[(m0 + ty * 4 + a) * O_DIM + o0 + tx * 4] = v;
    }
}

// ---------------------------------------------------------------------------
// Kernel 2: closed-form BN stats per (branch, f).
//   mean = (sumA + sumB) / (T*N)
//   E[y^2] = (N*(sumA2 + sumB2) + 2*sum_t SA_t*SB_t) / (T*N*N)
//   fold: s = g * rsqrt(var+eps), h = b - mean*s
// ---------------------------------------------------------------------------
__global__ void stats_kernel(const float* __restrict__ gamma1,
                             const float* __restrict__ beta1,
                             const float* __restrict__ gamma2,
                             const float* __restrict__ beta2) {
    const int bf = blockIdx.x;
    const int br = bf >> 7, f = bf & 127;
    const int colA = br * 256 + f;
    const int colB = colA + 128;
    const int tid = threadIdx.x;

    float sa = 0.f, sa2 = 0.f, sb = 0.f, sb2 = 0.f;
    #pragma unroll
    for (int k = 0; k < 8; k++) {
        int m = tid * 8 + k;
        float a = g_Y[m * O_DIM + colA];
        float b = g_Y[m * O_DIM + colB];
        sa += a;  sa2 = fmaf(a, a, sa2);
        sb += b;  sb2 = fmaf(b, b, sb2);
    }
    #pragma unroll
    for (int off = 16; off; off >>= 1) {
        sa  += __shfl_xor_sync(0xffffffffu, sa,  off);
        sa2 += __shfl_xor_sync(0xffffffffu, sa2, off);
        sb  += __shfl_xor_sync(0xffffffffu, sb,  off);
        sb2 += __shfl_xor_sync(0xffffffffu, sb2, off);
    }
    __shared__ float SA[8], SB[8], SA2[8], SB2[8];
    int w = tid >> 5;
    if ((tid & 31) == 0) { SA[w] = sa; SB[w] = sb; SA2[w] = sa2; SB2[w] = sb2; }
    __syncthreads();
    if (tid == 0) {
        float sumA = 0.f, sumB = 0.f, sumA2 = 0.f, sumB2 = 0.f, cross = 0.f;
        #pragma unroll
        for (int t = 0; t < 8; t++) {
            sumA  += SA[t];  sumB  += SB[t];
            sumA2 += SA2[t]; sumB2 += SB2[t];
            cross = fmaf(SA[t], SB[t], cross);
        }
        float mean = (sumA + sumB) * (1.0f / 2048.0f);
        float ey2  = (256.0f * (sumA2 + sumB2) + 2.0f * cross) * (1.0f / 524288.0f);
        float var  = ey2 - mean * mean;
        float g  = br ? gamma2[f] : gamma1[f];
        float bb = br ? beta2[f]  : beta1[f];
        float s  = g * rsqrtf(var + 1e-5f);
        g_sh[br * 256 + f]       = s;
        g_sh[br * 256 + 128 + f] = bb - mean * s;
    }
}

// ---------------------------------------------------------------------------
// Kernel 3: streaming epilogue (write-bound, 537 MB).
// 2048 blocks x 128 threads: block = (t, br, 8-row i-tile, j-quarter).
// 2048/148 = 13.8 blocks/SM -> wave-quantization tail ~1% (was 15.6% at 512).
// Warp w handles 16 j's; j OUTER, i inner: each b4 load reused for 8 i-rows,
// p[ii] = fma(a,s,h) in registers. Streaming stores (__stcs).
// ---------------------------------------------------------------------------
__global__ void __launch_bounds__(128) edge_kernel(float* __restrict__ out) {
    const int bid = blockIdx.x;          // 2048 blocks
    const int jq = bid & 3;
    const int itile = (bid >> 2) & 31;
    const int br = (bid >> 7) & 1;
    const int t = bid >> 8;
    const int i0 = itile * 8;
    const int tid = threadIdx.x;
    const int w = tid >> 5, l = tid & 31;
    const int f0 = l * 4;
    const int j0 = jq * 64 + w * 16;

    const float4 s4 = *(const float4*)&g_sh[br * 256 + f0];
    const float4 h4 = *(const float4*)&g_sh[br * 256 + 128 + f0];
    const int baseA = br * 256 + f0;
    const int baseB = baseA + 128;

    float4 p[8];
    #pragma unroll
    for (int ii = 0; ii < 8; ii++) {
        const float4 a4 = *(const float4*)&g_Y[(t * 256 + i0 + ii) * O_DIM + baseA];
        p[ii].x = fmaf(a4.x, s4.x, h4.x);
        p[ii].y = fmaf(a4.y, s4.y, h4.y);
        p[ii].z = fmaf(a4.z, s4.z, h4.z);
        p[ii].w = fmaf(a4.w, s4.w, h4.w);
    }

    // out index: (((t*2+br)*256 + i) * 256 + j) * 128 + f
    const size_t outbase = (size_t)((t * 2 + br) * 256 + i0) * (256 * 128);

    #pragma unroll 2
    for (int jj = 0; jj < 16; jj++) {
        const int j = j0 + jj;
        const float4 b4 = *(const float4*)&g_Y[(t * 256 + j) * O_DIM + baseB];
        float* orow = out + outbase + (size_t)j * 128 + f0;
        #pragma unroll
        for (int ii = 0; ii < 8; ii++) {
            float vx = fmaxf(fmaf(b4.x, s4.x, p[ii].x), 0.0f);
            float vy = fmaxf(fmaf(b4.y, s4.y, p[ii].y), 0.0f);
            float vz = fmaxf(fmaf(b4.z, s4.z, p[ii].z), 0.0f);
            float vw = fmaxf(fmaf(b4.w, s4.w, p[ii].w), 0.0f);
            if (j == i0 + ii) { vx = 0.f; vy = 0.f; vz = 0.f; vw = 0.f; }
            float sm = (vx + vy) + (vz + vw);
            #pragma unroll
            for (int off = 16; off; off >>= 1)
                sm += __shfl_xor_sync(0xffffffffu, sm, off);
            const float inv = __fdividef(1.0f, fmaxf(sm, 1e-12f));
            float4 o4 = make_float4(vx * inv, vy * inv, vz * inv, vw * inv);
            __stcs((float4*)(orow + (size_t)ii * (256 * 128)), o4);
        }
    }
}

// ---------------------------------------------------------------------------
extern "C" void kernel_launch(void* const* d_in, const int* in_sizes, int n_in,
                              void* d_out, int out_size) {
    const float* x  = (const float*)d_in[0];   // node_feats [8,256,128]
    const float* w1 = (const float*)d_in[1];   // [128,256]
    const float* g1 = (const float*)d_in[2];
    const float* b1 = (const float*)d_in[3];
    const float* w2 = (const float*)d_in[4];
    const float* g2 = (const float*)d_in[5];
    const float* b2 = (const float*)d_in[6];
    float* out = (float*)d_out;                // [8,2,256,256,128] fp32

    dim3 ggrid(O_DIM / 64, M_DIM / 64);        // (8, 32) = 256 blocks
    gemm_kernel<<<ggrid, 256>>>(x, w1, w2);
    stats_kernel<<<256, 256>>>(g1, b1, g2, b2);
    edge_kernel<<<2048, 128>>>(out);
}